// round 2
// baseline (speedup 1.0000x reference)
#include <cuda_runtime.h>
#include <math.h>

#define N_NODES 50000
#define E_EDGES 500000
#define P_PAIRS 200000
#define HDIM    128

// ---- scratch (device globals; no allocation in kernel_launch) ----
__device__ int   g_deg[N_NODES];
__device__ int   g_rowstart[N_NODES + 1];
__device__ int   g_cursor[N_NODES];
__device__ int   g_csr_src[E_EDGES];
__device__ float g_aggn[(size_t)N_NODES * HDIM];
__device__ float g_h1  [(size_t)N_NODES * HDIM];
__device__ float g_h2  [(size_t)N_NODES * HDIM];

// ---------------- CSR build ----------------
__global__ void zero_deg_kernel() {
    int i = blockIdx.x * blockDim.x + threadIdx.x;
    if (i < N_NODES) g_deg[i] = 0;
}

__global__ void count_deg_kernel(const int* __restrict__ dst, int E) {
    int i = blockIdx.x * blockDim.x + threadIdx.x;
    if (i < E) atomicAdd(&g_deg[dst[i]], 1);
}

__global__ void scan_deg_kernel(int E) {
    __shared__ int ssum[1024];
    int tid = threadIdx.x;
    const int chunk = (N_NODES + 1023) / 1024;  // 49
    int start = tid * chunk;
    int end = min(start + chunk, N_NODES);
    int s = 0;
    for (int i = start; i < end; i++) s += g_deg[i];
    ssum[tid] = s;
    __syncthreads();
    // Hillis-Steele inclusive scan over 1024 partials
    for (int d = 1; d < 1024; d <<= 1) {
        int v = (tid >= d) ? ssum[tid - d] : 0;
        __syncthreads();
        ssum[tid] += v;
        __syncthreads();
    }
    int run = ssum[tid] - s;  // exclusive prefix for my chunk
    for (int i = start; i < end; i++) {
        g_rowstart[i] = run;
        g_cursor[i]   = run;
        run += g_deg[i];
    }
    if (tid == 1023) g_rowstart[N_NODES] = E;
}

__global__ void fill_csr_kernel(const int* __restrict__ src,
                                const int* __restrict__ dst, int E) {
    int i = blockIdx.x * blockDim.x + threadIdx.x;
    if (i < E) {
        int p = atomicAdd(&g_cursor[dst[i]], 1);
        g_csr_src[p] = src[i];
    }
}

// ---------------- mean aggregation: warp per node, no float atomics ----------------
// use_h1 == 0: input = xin (external). use_h1 == 1: input = g_h1.
__global__ void agg_mean_kernel(const float* __restrict__ xin, int use_h1) {
    int gw   = (blockIdx.x * blockDim.x + threadIdx.x) >> 5;
    int lane = threadIdx.x & 31;
    if (gw >= N_NODES) return;
    const float* in = use_h1 ? g_h1 : xin;
    int s = g_rowstart[gw];
    int e = g_rowstart[gw + 1];
    float4 acc = make_float4(0.f, 0.f, 0.f, 0.f);
    for (int j = s; j < e; j++) {
        int srcn = g_csr_src[j];
        float4 v = *((const float4*)(in + (size_t)srcn * HDIM) + lane);
        acc.x += v.x; acc.y += v.y; acc.z += v.z; acc.w += v.w;
    }
    float inv = 1.0f / (float)max(e - s, 1);
    acc.x *= inv; acc.y *= inv; acc.z *= inv; acc.w *= inv;
    *((float4*)(g_aggn + (size_t)gw * HDIM) + lane) = acc;
}

// ---------------- fused SAGE layer GEMM: h = relu(agg@Wl^T + x@Wr^T + b) ----------------
// 256 threads. Thread t owns output unit u = t>>1, K-half kh = t&1.
// Weights for (u, kh-half) live in 128 registers. z row staged in smem.
// sel == 0: A2 = xin, out = g_h1. sel == 1: A2 = g_h1, out = g_h2.
__global__ __launch_bounds__(256, 1)
void sage_gemm_kernel(const float* __restrict__ xin,
                      const float* __restrict__ Wl, const float* __restrict__ Wr,
                      const float* __restrict__ bias, int sel, int M) {
    __shared__ __align__(16) float z[256];
    int t  = threadIdx.x;
    int u  = t >> 1;
    int kh = t & 1;
    const float* A2  = sel ? g_h1 : xin;
    float*       out = sel ? g_h2 : g_h1;
    const float* wp = (kh ? Wr : Wl) + u * HDIM;
    float w[128];
#pragma unroll
    for (int i = 0; i < 32; i++) {
        float4 v = ((const float4*)wp)[i];
        w[4 * i] = v.x; w[4 * i + 1] = v.y; w[4 * i + 2] = v.z; w[4 * i + 3] = v.w;
    }
    float bu = bias[u];
    for (int row = blockIdx.x; row < M; row += gridDim.x) {
        z[t] = (t < 128) ? g_aggn[(size_t)row * HDIM + t]
                         : A2[(size_t)row * HDIM + (t - 128)];
        __syncthreads();
        const float4* zz = (const float4*)(z + kh * 128);
        float a0 = 0.f, a1 = 0.f, a2 = 0.f, a3 = 0.f;
#pragma unroll
        for (int i = 0; i < 32; i++) {
            float4 v = zz[i];
            a0 = fmaf(w[4 * i],     v.x, a0);
            a1 = fmaf(w[4 * i + 1], v.y, a1);
            a2 = fmaf(w[4 * i + 2], v.z, a2);
            a3 = fmaf(w[4 * i + 3], v.w, a3);
        }
        float acc = (a0 + a1) + (a2 + a3);
        acc += __shfl_xor_sync(0xffffffffu, acc, 1);
        __syncthreads();  // z consumed; safe to restage next row
        if (kh == 0) out[(size_t)row * HDIM + u] = fmaxf(acc + bu, 0.0f);
    }
}

// ---------------- pair MLP head: sigmoid(relu([h2[a]|h2[b]]@W3^T + b3)@W4^T + b4) ----------------
__global__ __launch_bounds__(256, 1)
void pair_mlp_kernel(const int* __restrict__ pairs,
                     const float* __restrict__ W3, const float* __restrict__ b3,
                     const float* __restrict__ W4, const float* __restrict__ b4,
                     float* __restrict__ out, int P) {
    __shared__ __align__(16) float z[256];
    __shared__ float wsum[8];
    int t    = threadIdx.x;
    int u    = t >> 1;
    int kh   = t & 1;
    int lane = t & 31;
    int wid  = t >> 5;
    const float* wp = W3 + u * 256 + kh * 128;
    float w[128];
#pragma unroll
    for (int i = 0; i < 32; i++) {
        float4 v = ((const float4*)wp)[i];
        w[4 * i] = v.x; w[4 * i + 1] = v.y; w[4 * i + 2] = v.z; w[4 * i + 3] = v.w;
    }
    float b3u = b3[u];
    float w4u = W4[u];
    float b4v = b4[0];
    for (int p = blockIdx.x; p < P; p += gridDim.x) {
        int na = pairs[2 * p];
        int nb = pairs[2 * p + 1];
        z[t] = (t < 128) ? g_h2[(size_t)na * HDIM + t]
                         : g_h2[(size_t)nb * HDIM + (t - 128)];
        __syncthreads();
        const float4* zz = (const float4*)(z + kh * 128);
        float a0 = 0.f, a1 = 0.f, a2 = 0.f, a3 = 0.f;
#pragma unroll
        for (int i = 0; i < 32; i++) {
            float4 v = zz[i];
            a0 = fmaf(w[4 * i],     v.x, a0);
            a1 = fmaf(w[4 * i + 1], v.y, a1);
            a2 = fmaf(w[4 * i + 2], v.z, a2);
            a3 = fmaf(w[4 * i + 3], v.w, a3);
        }
        float acc = (a0 + a1) + (a2 + a3);
        acc += __shfl_xor_sync(0xffffffffu, acc, 1);  // combine K-halves
        float term = (kh == 0) ? fmaxf(acc + b3u, 0.0f) * w4u : 0.0f;
#pragma unroll
        for (int o = 16; o > 0; o >>= 1)
            term += __shfl_xor_sync(0xffffffffu, term, o);
        if (lane == 0) wsum[wid] = term;
        __syncthreads();
        if (t == 0) {
            float s = b4v;
#pragma unroll
            for (int i = 0; i < 8; i++) s += wsum[i];
            out[p] = 1.0f / (1.0f + expf(-s));
        }
        __syncthreads();  // protect z + wsum before next iteration
    }
}

// ---------------- launch ----------------
extern "C" void kernel_launch(void* const* d_in, const int* in_sizes, int n_in,
                              void* d_out, int out_size) {
    const float* x    = (const float*)d_in[0];
    const int*   edge = (const int*)d_in[1];
    const int*   prs  = (const int*)d_in[2];
    const float* Wl1  = (const float*)d_in[3];
    const float* Wr1  = (const float*)d_in[4];
    const float* b1   = (const float*)d_in[5];
    const float* Wl2  = (const float*)d_in[6];
    const float* Wr2  = (const float*)d_in[7];
    const float* b2   = (const float*)d_in[8];
    const float* W3   = (const float*)d_in[9];
    const float* b3   = (const float*)d_in[10];
    const float* W4   = (const float*)d_in[11];
    const float* b4   = (const float*)d_in[12];
    float* out = (float*)d_out;

    const int E = in_sizes[1] / 2;   // 500000
    const int P = in_sizes[2] / 2;   // 200000
    const int M = N_NODES;
    const int* src = edge;
    const int* dst = edge + E;

    // CSR build (by dst)
    zero_deg_kernel<<<(N_NODES + 255) / 256, 256>>>();
    count_deg_kernel<<<(E + 255) / 256, 256>>>(dst, E);
    scan_deg_kernel<<<1, 1024>>>(E);
    fill_csr_kernel<<<(E + 255) / 256, 256>>>(src, dst, E);

    const int aggBlocks = (N_NODES * 32 + 255) / 256;

    // Layer 1
    agg_mean_kernel<<<aggBlocks, 256>>>(x, 0);
    sage_gemm_kernel<<<1480, 256>>>(x, Wl1, Wr1, b1, 0, M);
    // Layer 2
    agg_mean_kernel<<<aggBlocks, 256>>>(x, 1);
    sage_gemm_kernel<<<1480, 256>>>(x, Wl2, Wr2, b2, 1, M);
    // Pair head
    pair_mlp_kernel<<<1480, 256>>>(prs, W3, b3, W4, b4, out, P);
}

// round 3
// speedup vs baseline: 3.6148x; 3.6148x over previous
#include <cuda_runtime.h>
#include <math.h>

#define N_NODES 50000
#define E_EDGES 500000
#define HDIM    128

#define BM 64
#define BN 128
#define BK 32
#define TM 8
#define TN 4

// ---- scratch (device globals; no allocation in kernel_launch) ----
__device__ int   g_deg[N_NODES];
__device__ int   g_rowstart[N_NODES + 1];
__device__ int   g_cursor[N_NODES];
__device__ int   g_csr_src[E_EDGES];
__device__ float g_aggn[(size_t)N_NODES * HDIM];
__device__ float g_h1  [(size_t)N_NODES * HDIM];
__device__ float g_h2  [(size_t)N_NODES * HDIM];
__device__ float g_U   [(size_t)N_NODES * 256];   // [Ua | Ub] per node

// ---------------- CSR build ----------------
__global__ void zero_deg_kernel() {
    int i = blockIdx.x * blockDim.x + threadIdx.x;
    if (i < N_NODES) g_deg[i] = 0;
}

__global__ void count_deg_kernel(const int* __restrict__ dst, int E) {
    int i = blockIdx.x * blockDim.x + threadIdx.x;
    if (i < E) atomicAdd(&g_deg[dst[i]], 1);
}

__global__ void scan_deg_kernel(int E) {
    __shared__ int ssum[1024];
    int tid = threadIdx.x;
    const int chunk = (N_NODES + 1023) / 1024;  // 49
    int start = tid * chunk;
    int end = min(start + chunk, N_NODES);
    int s = 0;
    for (int i = start; i < end; i++) s += g_deg[i];
    ssum[tid] = s;
    __syncthreads();
    for (int d = 1; d < 1024; d <<= 1) {
        int v = (tid >= d) ? ssum[tid - d] : 0;
        __syncthreads();
        ssum[tid] += v;
        __syncthreads();
    }
    int run = ssum[tid] - s;
    for (int i = start; i < end; i++) {
        g_rowstart[i] = run;
        g_cursor[i]   = run;
        run += g_deg[i];
    }
    if (tid == 1023) g_rowstart[N_NODES] = E;
}

__global__ void fill_csr_kernel(const int* __restrict__ src,
                                const int* __restrict__ dst, int E) {
    int i = blockIdx.x * blockDim.x + threadIdx.x;
    if (i < E) {
        int p = atomicAdd(&g_cursor[dst[i]], 1);
        g_csr_src[p] = src[i];
    }
}

// ---------------- mean aggregation: warp per node ----------------
__global__ void agg_mean_kernel(const float* __restrict__ xin, int use_h1) {
    int gw   = (blockIdx.x * blockDim.x + threadIdx.x) >> 5;
    int lane = threadIdx.x & 31;
    if (gw >= N_NODES) return;
    const float* in = use_h1 ? g_h1 : xin;
    int s = g_rowstart[gw];
    int e = g_rowstart[gw + 1];
    float4 acc = make_float4(0.f, 0.f, 0.f, 0.f);
    int j = s;
    for (; j + 4 <= e; j += 4) {
        int s0 = g_csr_src[j], s1 = g_csr_src[j + 1];
        int s2 = g_csr_src[j + 2], s3 = g_csr_src[j + 3];
        float4 v0 = *((const float4*)(in + (size_t)s0 * HDIM) + lane);
        float4 v1 = *((const float4*)(in + (size_t)s1 * HDIM) + lane);
        float4 v2 = *((const float4*)(in + (size_t)s2 * HDIM) + lane);
        float4 v3 = *((const float4*)(in + (size_t)s3 * HDIM) + lane);
        acc.x += v0.x; acc.y += v0.y; acc.z += v0.z; acc.w += v0.w;
        acc.x += v1.x; acc.y += v1.y; acc.z += v1.z; acc.w += v1.w;
        acc.x += v2.x; acc.y += v2.y; acc.z += v2.z; acc.w += v2.w;
        acc.x += v3.x; acc.y += v3.y; acc.z += v3.z; acc.w += v3.w;
    }
    for (; j < e; j++) {
        int sn = g_csr_src[j];
        float4 v = *((const float4*)(in + (size_t)sn * HDIM) + lane);
        acc.x += v.x; acc.y += v.y; acc.z += v.z; acc.w += v.w;
    }
    float inv = 1.0f / (float)max(e - s, 1);
    acc.x *= inv; acc.y *= inv; acc.z *= inv; acc.w *= inv;
    *((float4*)(g_aggn + (size_t)gw * HDIM) + lane) = acc;
}

// ---------------- shared inner MMA for 64x128 tile, one 32-k chunk ----------------
__device__ __forceinline__ void mma_chunk(const float As2[BM][BK],
                                          const float Ws[BK][BN + 4],
                                          int tr, int tc, float acc[TM][TN]) {
#pragma unroll
    for (int k0 = 0; k0 < BK; k0 += 4) {
        float4 a[TM];
#pragma unroll
        for (int r = 0; r < TM; r++)
            a[r] = *(const float4*)&As2[tr * TM + r][k0];
#pragma unroll
        for (int jj = 0; jj < 4; jj++) {
            float4 b = *(const float4*)&Ws[k0 + jj][tc * TN];
#pragma unroll
            for (int r = 0; r < TM; r++) {
                float av = (jj == 0) ? a[r].x : (jj == 1) ? a[r].y : (jj == 2) ? a[r].z : a[r].w;
                acc[r][0] = fmaf(av, b.x, acc[r][0]);
                acc[r][1] = fmaf(av, b.y, acc[r][1]);
                acc[r][2] = fmaf(av, b.z, acc[r][2]);
                acc[r][3] = fmaf(av, b.w, acc[r][3]);
            }
        }
    }
}

// ---------------- SAGE layer GEMM: out = relu([agg|Asec] @ [Wl|Wr]^T + b) ----------------
__global__ __launch_bounds__(256, 2)
void layer_gemm_kernel(const float* __restrict__ Asec,
                       const float* __restrict__ Wl, const float* __restrict__ Wr,
                       const float* __restrict__ bias, float* __restrict__ out, int M) {
    __shared__ float As2[BM][BK];
    __shared__ float Ws[BK][BN + 4];
    int t  = threadIdx.x;
    int tc = t & 31;
    int tr = t >> 5;
    int m0 = blockIdx.x * BM;
    float acc[TM][TN];
#pragma unroll
    for (int r = 0; r < TM; r++)
#pragma unroll
        for (int c = 0; c < TN; c++) acc[r][c] = 0.f;

    for (int kc = 0; kc < 8; kc++) {
        const float* Achunk = (kc < 4) ? g_aggn : Asec;
        const float* Wsrc   = (kc < 4) ? Wl : Wr;
        int kbase = (kc & 3) * BK;
        // A tile: 64 rows x 32 k, m-major
#pragma unroll
        for (int it = 0; it < 2; it++) {
            int j   = t + it * 256;
            int row = j >> 3;
            int kq  = j & 7;
            int gr  = min(m0 + row, M - 1);
            float4 v = *(const float4*)(Achunk + (size_t)gr * HDIM + kbase + kq * 4);
            *(float4*)&As2[row][kq * 4] = v;
        }
        // W tile: transpose-store to k-major [BK][BN+4]
#pragma unroll
        for (int it = 0; it < 4; it++) {
            int j  = t + it * 256;
            int n  = j >> 3;
            int kq = j & 7;
            float4 v = *(const float4*)(Wsrc + (size_t)n * HDIM + kbase + kq * 4);
            Ws[kq * 4 + 0][n] = v.x;
            Ws[kq * 4 + 1][n] = v.y;
            Ws[kq * 4 + 2][n] = v.z;
            Ws[kq * 4 + 3][n] = v.w;
        }
        __syncthreads();
        mma_chunk(As2, Ws, tr, tc, acc);
        __syncthreads();
    }
    float4 bv = *(const float4*)(bias + tc * TN);
#pragma unroll
    for (int r = 0; r < TM; r++) {
        int gr = m0 + tr * TM + r;
        if (gr < M) {
            float4 o;
            o.x = fmaxf(acc[r][0] + bv.x, 0.f);
            o.y = fmaxf(acc[r][1] + bv.y, 0.f);
            o.z = fmaxf(acc[r][2] + bv.z, 0.f);
            o.w = fmaxf(acc[r][3] + bv.w, 0.f);
            *(float4*)(out + (size_t)gr * HDIM + tc * TN) = o;
        }
    }
}

// ---------------- U GEMM: U[:, y*128..] = h2 @ W3half^T (no bias/relu) ----------------
// y=0: weight row n -> W3 + n*256 (left K-half); y=1: -> W3 + n*256 + 128 (right K-half)
__global__ __launch_bounds__(256, 2)
void u_gemm_kernel(const float* __restrict__ W3, int M) {
    __shared__ float As2[BM][BK];
    __shared__ float Ws[BK][BN + 4];
    int t  = threadIdx.x;
    int tc = t & 31;
    int tr = t >> 5;
    int m0 = blockIdx.x * BM;
    int y  = blockIdx.y;
    const float* Wbase = W3 + y * 128;
    float acc[TM][TN];
#pragma unroll
    for (int r = 0; r < TM; r++)
#pragma unroll
        for (int c = 0; c < TN; c++) acc[r][c] = 0.f;

    for (int kc = 0; kc < 4; kc++) {
        int kbase = kc * BK;
#pragma unroll
        for (int it = 0; it < 2; it++) {
            int j   = t + it * 256;
            int row = j >> 3;
            int kq  = j & 7;
            int gr  = min(m0 + row, M - 1);
            float4 v = *(const float4*)(g_h2 + (size_t)gr * HDIM + kbase + kq * 4);
            *(float4*)&As2[row][kq * 4] = v;
        }
#pragma unroll
        for (int it = 0; it < 4; it++) {
            int j  = t + it * 256;
            int n  = j >> 3;
            int kq = j & 7;
            float4 v = *(const float4*)(Wbase + (size_t)n * 256 + kbase + kq * 4);
            Ws[kq * 4 + 0][n] = v.x;
            Ws[kq * 4 + 1][n] = v.y;
            Ws[kq * 4 + 2][n] = v.z;
            Ws[kq * 4 + 3][n] = v.w;
        }
        __syncthreads();
        mma_chunk(As2, Ws, tr, tc, acc);
        __syncthreads();
    }
#pragma unroll
    for (int r = 0; r < TM; r++) {
        int gr = m0 + tr * TM + r;
        if (gr < M) {
            float4 o = make_float4(acc[r][0], acc[r][1], acc[r][2], acc[r][3]);
            *(float4*)(g_U + (size_t)gr * 256 + y * 128 + tc * TN) = o;
        }
    }
}

// ---------------- pair head: sigmoid(W4 . relu(Ua[a]+Ub[b]+b3) + b4) ----------------
__global__ __launch_bounds__(256)
void pair_kernel(const int* __restrict__ pairs,
                 const float* __restrict__ b3, const float* __restrict__ W4,
                 const float* __restrict__ b4, float* __restrict__ out, int P) {
    int w    = (blockIdx.x * blockDim.x + threadIdx.x) >> 5;
    int lane = threadIdx.x & 31;
    if (w >= P) return;
    int na = __ldg(&pairs[2 * w]);
    int nb = __ldg(&pairs[2 * w + 1]);
    float4 ua = *((const float4*)(g_U + (size_t)na * 256) + lane);
    float4 ub = *((const float4*)(g_U + (size_t)nb * 256 + 128) + lane);
    float4 bv = *((const float4*)b3 + lane);
    float4 wv = *((const float4*)W4 + lane);
    float s = fmaxf(ua.x + ub.x + bv.x, 0.f) * wv.x
            + fmaxf(ua.y + ub.y + bv.y, 0.f) * wv.y
            + fmaxf(ua.z + ub.z + bv.z, 0.f) * wv.z
            + fmaxf(ua.w + ub.w + bv.w, 0.f) * wv.w;
#pragma unroll
    for (int o = 16; o > 0; o >>= 1)
        s += __shfl_xor_sync(0xffffffffu, s, o);
    if (lane == 0) out[w] = 1.0f / (1.0f + expf(-(s + b4[0])));
}

// ---------------- launch ----------------
extern "C" void kernel_launch(void* const* d_in, const int* in_sizes, int n_in,
                              void* d_out, int out_size) {
    const float* x    = (const float*)d_in[0];
    const int*   edge = (const int*)d_in[1];
    const int*   prs  = (const int*)d_in[2];
    const float* Wl1  = (const float*)d_in[3];
    const float* Wr1  = (const float*)d_in[4];
    const float* b1   = (const float*)d_in[5];
    const float* Wl2  = (const float*)d_in[6];
    const float* Wr2  = (const float*)d_in[7];
    const float* b2   = (const float*)d_in[8];
    const float* W3   = (const float*)d_in[9];
    const float* b3   = (const float*)d_in[10];
    const float* W4   = (const float*)d_in[11];
    const float* b4   = (const float*)d_in[12];
    float* out = (float*)d_out;

    const int E = in_sizes[1] / 2;
    const int P = in_sizes[2] / 2;
    const int M = N_NODES;
    const int* src = edge;
    const int* dst = edge + E;

    float* g_h1_p;  cudaGetSymbolAddress((void**)&g_h1_p, g_h1);
    float* g_h2_p;  cudaGetSymbolAddress((void**)&g_h2_p, g_h2);

    // CSR build (by dst)
    zero_deg_kernel<<<(N_NODES + 255) / 256, 256>>>();
    count_deg_kernel<<<(E + 255) / 256, 256>>>(dst, E);
    scan_deg_kernel<<<1, 1024>>>(E);
    fill_csr_kernel<<<(E + 255) / 256, 256>>>(src, dst, E);

    const int aggBlocks = (N_NODES * 32 + 255) / 256;
    const int mTiles = (M + BM - 1) / BM;

    // Layer 1
    agg_mean_kernel<<<aggBlocks, 256>>>(x, 0);
    layer_gemm_kernel<<<mTiles, 256>>>(x, Wl1, Wr1, b1, g_h1_p, M);
    // Layer 2
    agg_mean_kernel<<<aggBlocks, 256>>>(x, 1);
    layer_gemm_kernel<<<mTiles, 256>>>(g_h1_p, Wl2, Wr2, b2, g_h2_p, M);
    // Precompute U = h2 @ [W3_left ; W3_right]^T
    u_gemm_kernel<<<dim3(mTiles, 2), 256>>>(W3, M);
    // Pair head
    pair_kernel<<<(P * 32 + 255) / 256, 256>>>(prs, b3, W4, b4, out, P);
}

// round 5
// speedup vs baseline: 4.3972x; 1.2164x over previous
#include <cuda_runtime.h>
#include <math.h>

#define N_NODES 50000
#define E_EDGES 500000
#define HDIM    128

// f32x2 GEMM tile config
#define BM 64
#define BN 128
#define BK 32
#define TM 4
#define TN 8

// packed fp32 helpers (FFMA2 path; bitwise-exact fp32)
#define FMA2(acc, a, b)  asm("fma.rn.f32x2 %0, %1, %2, %0;" : "+l"(acc) : "l"(a), "l"(b))
#define DUP2(d, s)       asm("mov.b64 %0, {%1, %1};" : "=l"(d) : "f"(s))
#define UNPK2(lo, hi, d) asm("mov.b64 {%0, %1}, %2;" : "=f"(lo), "=f"(hi) : "l"(d))

// ---- scratch (device globals; no allocation in kernel_launch) ----
__device__ int   g_deg[N_NODES];
__device__ int   g_rowstart[N_NODES + 1];
__device__ int   g_cursor[N_NODES];
__device__ int   g_csr_src[E_EDGES];
__device__ float g_aggn[(size_t)N_NODES * HDIM];
__device__ float g_h1  [(size_t)N_NODES * HDIM];
__device__ float g_h2  [(size_t)N_NODES * HDIM];
__device__ float g_U   [(size_t)N_NODES * 256];   // [Ua | Ub] per node

// ---------------- CSR build ----------------
__global__ void zero_deg_kernel() {
    int i = blockIdx.x * blockDim.x + threadIdx.x;
    if (i < N_NODES) g_deg[i] = 0;
}

__global__ void count_deg_kernel(const int* __restrict__ dst, int E) {
    int i = blockIdx.x * blockDim.x + threadIdx.x;
    if (i < E) atomicAdd(&g_deg[dst[i]], 1);
}

__global__ void scan_deg_kernel(int E) {
    __shared__ int ssum[1024];
    int tid = threadIdx.x;
    const int chunk = (N_NODES + 1023) / 1024;  // 49
    int start = tid * chunk;
    int end = min(start + chunk, N_NODES);
    int s = 0;
    for (int i = start; i < end; i++) s += g_deg[i];
    ssum[tid] = s;
    __syncthreads();
    for (int d = 1; d < 1024; d <<= 1) {
        int v = (tid >= d) ? ssum[tid - d] : 0;
        __syncthreads();
        ssum[tid] += v;
        __syncthreads();
    }
    int run = ssum[tid] - s;
    for (int i = start; i < end; i++) {
        g_rowstart[i] = run;
        g_cursor[i]   = run;
        run += g_deg[i];
    }
    if (tid == 1023) g_rowstart[N_NODES] = E;
}

__global__ void fill_csr_kernel(const int* __restrict__ src,
                                const int* __restrict__ dst, int E) {
    int i = blockIdx.x * blockDim.x + threadIdx.x;
    if (i < E) {
        int p = atomicAdd(&g_cursor[dst[i]], 1);
        g_csr_src[p] = src[i];
    }
}

// ---------------- mean aggregation: warp per node ----------------
__global__ void agg_mean_kernel(const float* __restrict__ xin, int use_h1) {
    int gw   = (blockIdx.x * blockDim.x + threadIdx.x) >> 5;
    int lane = threadIdx.x & 31;
    if (gw >= N_NODES) return;
    const float* in = use_h1 ? g_h1 : xin;
    int s = g_rowstart[gw];
    int e = g_rowstart[gw + 1];
    float4 acc = make_float4(0.f, 0.f, 0.f, 0.f);
    int j = s;
    for (; j + 4 <= e; j += 4) {
        int s0 = g_csr_src[j], s1 = g_csr_src[j + 1];
        int s2 = g_csr_src[j + 2], s3 = g_csr_src[j + 3];
        float4 v0 = *((const float4*)(in + (size_t)s0 * HDIM) + lane);
        float4 v1 = *((const float4*)(in + (size_t)s1 * HDIM) + lane);
        float4 v2 = *((const float4*)(in + (size_t)s2 * HDIM) + lane);
        float4 v3 = *((const float4*)(in + (size_t)s3 * HDIM) + lane);
        acc.x += v0.x; acc.y += v0.y; acc.z += v0.z; acc.w += v0.w;
        acc.x += v1.x; acc.y += v1.y; acc.z += v1.z; acc.w += v1.w;
        acc.x += v2.x; acc.y += v2.y; acc.z += v2.z; acc.w += v2.w;
        acc.x += v3.x; acc.y += v3.y; acc.z += v3.z; acc.w += v3.w;
    }
    for (; j < e; j++) {
        int sn = g_csr_src[j];
        float4 v = *((const float4*)(in + (size_t)sn * HDIM) + lane);
        acc.x += v.x; acc.y += v.y; acc.z += v.z; acc.w += v.w;
    }
    float inv = 1.0f / (float)max(e - s, 1);
    acc.x *= inv; acc.y *= inv; acc.z *= inv; acc.w *= inv;
    *((float4*)(g_aggn + (size_t)gw * HDIM) + lane) = acc;
}

// ---------------- f32x2 inner MMA: 64x128 tile, one 32-k chunk ----------------
// acc[r][c2]: row tr*TM+r, packed col pair (tc*TN + 2*c2, +1)
__device__ __forceinline__ void mma_chunk2(const float As[BM][BK],
                                           const float Ws[BK][BN + 4],
                                           int tr, int tc,
                                           unsigned long long acc[TM][TN / 2]) {
#pragma unroll
    for (int k0 = 0; k0 < BK; k0 += 4) {
        float4 a[TM];
#pragma unroll
        for (int r = 0; r < TM; r++)
            a[r] = *(const float4*)&As[tr * TM + r][k0];
#pragma unroll
        for (int jj = 0; jj < 4; jj++) {
            ulonglong2 b01 = *(const ulonglong2*)&Ws[k0 + jj][tc * TN];
            ulonglong2 b23 = *(const ulonglong2*)&Ws[k0 + jj][tc * TN + 4];
#pragma unroll
            for (int r = 0; r < TM; r++) {
                float av = (jj == 0) ? a[r].x : (jj == 1) ? a[r].y : (jj == 2) ? a[r].z : a[r].w;
                unsigned long long av2;
                DUP2(av2, av);
                FMA2(acc[r][0], av2, b01.x);
                FMA2(acc[r][1], av2, b01.y);
                FMA2(acc[r][2], av2, b23.x);
                FMA2(acc[r][3], av2, b23.y);
            }
        }
    }
}

// ---------------- SAGE layer GEMM: out = relu([agg|Asec] @ [Wl|Wr]^T + b) ----------------
__global__ __launch_bounds__(256, 3)
void layer_gemm_kernel(const float* __restrict__ Asec,
                       const float* __restrict__ Wl, const float* __restrict__ Wr,
                       const float* __restrict__ bias, float* __restrict__ out, int M) {
    __shared__ float As[BM][BK];
    __shared__ float Ws[BK][BN + 4];
    int t  = threadIdx.x;
    int tc = t & 15;
    int tr = t >> 4;
    int m0 = blockIdx.x * BM;
    unsigned long long acc[TM][TN / 2];
#pragma unroll
    for (int r = 0; r < TM; r++)
#pragma unroll
        for (int c = 0; c < TN / 2; c++) acc[r][c] = 0ULL;

    for (int kc = 0; kc < 8; kc++) {
        const float* Achunk = (kc < 4) ? g_aggn : Asec;
        const float* Wsrc   = (kc < 4) ? Wl : Wr;
        int kbase = (kc & 3) * BK;
        // A tile: 64 x 32, 2 float4 per thread
#pragma unroll
        for (int it = 0; it < 2; it++) {
            int j   = t + it * 256;
            int row = j >> 3;
            int kq  = j & 7;
            int gr  = min(m0 + row, M - 1);
            *(float4*)&As[row][kq * 4] =
                *(const float4*)(Achunk + (size_t)gr * HDIM + kbase + kq * 4);
        }
        // W tile transpose-store: 128 n x 32 k -> k-major
#pragma unroll
        for (int it = 0; it < 4; it++) {
            int j  = t + it * 256;
            int n  = j >> 3;
            int kq = j & 7;
            float4 v = *(const float4*)(Wsrc + (size_t)n * HDIM + kbase + kq * 4);
            Ws[kq * 4 + 0][n] = v.x;
            Ws[kq * 4 + 1][n] = v.y;
            Ws[kq * 4 + 2][n] = v.z;
            Ws[kq * 4 + 3][n] = v.w;
        }
        __syncthreads();
        mma_chunk2(As, Ws, tr, tc, acc);
        __syncthreads();
    }
    // epilogue: unpack, +bias, relu, store
    float4 b0 = *(const float4*)(bias + tc * TN);
    float4 b1 = *(const float4*)(bias + tc * TN + 4);
#pragma unroll
    for (int r = 0; r < TM; r++) {
        int gr = m0 + tr * TM + r;
        if (gr < M) {
            float v0, v1, v2, v3, v4, v5, v6, v7;
            UNPK2(v0, v1, acc[r][0]);
            UNPK2(v2, v3, acc[r][1]);
            UNPK2(v4, v5, acc[r][2]);
            UNPK2(v6, v7, acc[r][3]);
            float4 o0, o1;
            o0.x = fmaxf(v0 + b0.x, 0.f); o0.y = fmaxf(v1 + b0.y, 0.f);
            o0.z = fmaxf(v2 + b0.z, 0.f); o0.w = fmaxf(v3 + b0.w, 0.f);
            o1.x = fmaxf(v4 + b1.x, 0.f); o1.y = fmaxf(v5 + b1.y, 0.f);
            o1.z = fmaxf(v6 + b1.z, 0.f); o1.w = fmaxf(v7 + b1.w, 0.f);
            *(float4*)(out + (size_t)gr * HDIM + tc * TN)     = o0;
            *(float4*)(out + (size_t)gr * HDIM + tc * TN + 4) = o1;
        }
    }
}

// ---------------- U GEMM: U[:, y*128..] = h2 @ W3half^T (no bias/relu) ----------------
__global__ __launch_bounds__(256, 3)
void u_gemm_kernel(const float* __restrict__ W3, int M) {
    __shared__ float As[BM][BK];
    __shared__ float Ws[BK][BN + 4];
    int t  = threadIdx.x;
    int tc = t & 15;
    int tr = t >> 4;
    int m0 = blockIdx.x * BM;
    int y  = blockIdx.y;
    const float* Wbase = W3 + y * 128;
    unsigned long long acc[TM][TN / 2];
#pragma unroll
    for (int r = 0; r < TM; r++)
#pragma unroll
        for (int c = 0; c < TN / 2; c++) acc[r][c] = 0ULL;

    for (int kc = 0; kc < 4; kc++) {
        int kbase = kc * BK;
#pragma unroll
        for (int it = 0; it < 2; it++) {
            int j   = t + it * 256;
            int row = j >> 3;
            int kq  = j & 7;
            int gr  = min(m0 + row, M - 1);
            *(float4*)&As[row][kq * 4] =
                *(const float4*)(g_h2 + (size_t)gr * HDIM + kbase + kq * 4);
        }
#pragma unroll
        for (int it = 0; it < 4; it++) {
            int j  = t + it * 256;
            int n  = j >> 3;
            int kq = j & 7;
            float4 v = *(const float4*)(Wbase + (size_t)n * 256 + kbase + kq * 4);
            Ws[kq * 4 + 0][n] = v.x;
            Ws[kq * 4 + 1][n] = v.y;
            Ws[kq * 4 + 2][n] = v.z;
            Ws[kq * 4 + 3][n] = v.w;
        }
        __syncthreads();
        mma_chunk2(As, Ws, tr, tc, acc);
        __syncthreads();
    }
#pragma unroll
    for (int r = 0; r < TM; r++) {
        int gr = m0 + tr * TM + r;
        if (gr < M) {
            float v0, v1, v2, v3, v4, v5, v6, v7;
            UNPK2(v0, v1, acc[r][0]);
            UNPK2(v2, v3, acc[r][1]);
            UNPK2(v4, v5, acc[r][2]);
            UNPK2(v6, v7, acc[r][3]);
            float* op = g_U + (size_t)gr * 256 + y * 128 + tc * TN;
            *(float4*)op       = make_float4(v0, v1, v2, v3);
            *(float4*)(op + 4) = make_float4(v4, v5, v6, v7);
        }
    }
}

// ---------------- pair head: sigmoid(W4 . relu(Ua[a]+Ub[b]+b3) + b4) ----------------
__global__ __launch_bounds__(256)
void pair_kernel(const int* __restrict__ pairs,
                 const float* __restrict__ b3, const float* __restrict__ W4,
                 const float* __restrict__ b4, float* __restrict__ out, int P) {
    int w    = (blockIdx.x * blockDim.x + threadIdx.x) >> 5;
    int lane = threadIdx.x & 31;
    if (w >= P) return;
    int na = __ldg(&pairs[2 * w]);
    int nb = __ldg(&pairs[2 * w + 1]);
    float4 ua = *((const float4*)(g_U + (size_t)na * 256) + lane);
    float4 ub = *((const float4*)(g_U + (size_t)nb * 256 + 128) + lane);
    float4 bv = *((const float4*)b3 + lane);
    float4 wv = *((const float4*)W4 + lane);
    float s = fmaxf(ua.x + ub.x + bv.x, 0.f) * wv.x
            + fmaxf(ua.y + ub.y + bv.y, 0.f) * wv.y
            + fmaxf(ua.z + ub.z + bv.z, 0.f) * wv.z
            + fmaxf(ua.w + ub.w + bv.w, 0.f) * wv.w;
#pragma unroll
    for (int o = 16; o > 0; o >>= 1)
        s += __shfl_xor_sync(0xffffffffu, s, o);
    if (lane == 0) out[w] = 1.0f / (1.0f + expf(-(s + b4[0])));
}

// ---------------- launch ----------------
extern "C" void kernel_launch(void* const* d_in, const int* in_sizes, int n_in,
                              void* d_out, int out_size) {
    const float* x    = (const float*)d_in[0];
    const int*   edge = (const int*)d_in[1];
    const int*   prs  = (const int*)d_in[2];
    const float* Wl1  = (const float*)d_in[3];
    const float* Wr1  = (const float*)d_in[4];
    const float* b1   = (const float*)d_in[5];
    const float* Wl2  = (const float*)d_in[6];
    const float* Wr2  = (const float*)d_in[7];
    const float* b2   = (const float*)d_in[8];
    const float* W3   = (const float*)d_in[9];
    const float* b3   = (const float*)d_in[10];
    const float* W4   = (const float*)d_in[11];
    const float* b4   = (const float*)d_in[12];
    float* out = (float*)d_out;

    const int E = in_sizes[1] / 2;
    const int P = in_sizes[2] / 2;
    const int M = N_NODES;
    const int* src = edge;
    const int* dst = edge + E;

    float* g_h1_p;  cudaGetSymbolAddress((void**)&g_h1_p, g_h1);
    float* g_h2_p;  cudaGetSymbolAddress((void**)&g_h2_p, g_h2);

    // CSR build (by dst)
    zero_deg_kernel<<<(N_NODES + 255) / 256, 256>>>();
    count_deg_kernel<<<(E + 255) / 256, 256>>>(dst, E);
    scan_deg_kernel<<<1, 1024>>>(E);
    fill_csr_kernel<<<(E + 255) / 256, 256>>>(src, dst, E);

    const int aggBlocks = (N_NODES * 32 + 255) / 256;
    const int mTiles = (M + BM - 1) / BM;

    // Layer 1
    agg_mean_kernel<<<aggBlocks, 256>>>(x, 0);
    layer_gemm_kernel<<<mTiles, 256>>>(x, Wl1, Wr1, b1, g_h1_p, M);
    // Layer 2
    agg_mean_kernel<<<aggBlocks, 256>>>(x, 1);
    layer_gemm_kernel<<<mTiles, 256>>>(g_h1_p, Wl2, Wr2, b2, g_h2_p, M);
    // Precompute U = h2 @ [W3_left ; W3_right]^T
    u_gemm_kernel<<<dim3(mTiles, 2), 256>>>(W3, M);
    // Pair head
    pair_kernel<<<(P * 32 + 255) / 256, 256>>>(prs, b3, W4, b4, out, P);
}